// round 1
// baseline (speedup 1.0000x reference)
#include <cuda_runtime.h>
#include <math.h>

// Problem constants (fixed by the dataset)
#define A_   16
#define SK_  2048
#define SQ_  2048
#define D_   128
#define IDM_ 128
#define RR_  3
// T_ANNEAL = 10, t_ANNEAL = 0

// ---------------------------------------------------------------------------
// Scratch (device globals — no allocation allowed)
// ---------------------------------------------------------------------------
// Folded projection matrices: M[a][d][r] = sum_e Wx[e,d] * W[a,e,r]
// layout: a*384 + d*3 + r  (contiguous 12 floats per 4 d's per lane)
__device__ float  g_M[2][A_ * IDM_ * RR_];   // [0] = K-side, [1] = Q-side
__device__ float  g_c[2][A_ * RR_];          // folded bias projections
// Hash codes, padded to float4 per row.  K-codes pre-scaled by 1/R.
__device__ float4 g_code[2][A_ * SK_];       // [0] = Kc/3, [1] = Qc

// ---------------------------------------------------------------------------
// Kernel 1: fold Wk/Wq + bias through W[a]  (tiny: 16 blocks x 128 threads)
// ---------------------------------------------------------------------------
__global__ void prep_kernel(const float* __restrict__ Wk, const float* __restrict__ bk,
                            const float* __restrict__ Wq, const float* __restrict__ bq,
                            const float* __restrict__ W) {
    int a = blockIdx.x;
    int d = threadIdx.x;   // 0..127
    __shared__ float Wsh[IDM_ * RR_];   // W[a] : [128,3]
    for (int i = d; i < IDM_ * RR_; i += IDM_) Wsh[i] = W[a * IDM_ * RR_ + i];
    __syncthreads();

    float ak0 = 0.f, ak1 = 0.f, ak2 = 0.f;
    float aq0 = 0.f, aq1 = 0.f, aq2 = 0.f;
#pragma unroll 4
    for (int e = 0; e < IDM_; e++) {
        float wk = Wk[e * D_ + d];      // coalesced across threads
        float wq = Wq[e * D_ + d];
        float w0 = Wsh[e * 3 + 0], w1 = Wsh[e * 3 + 1], w2 = Wsh[e * 3 + 2];
        ak0 = fmaf(wk, w0, ak0); ak1 = fmaf(wk, w1, ak1); ak2 = fmaf(wk, w2, ak2);
        aq0 = fmaf(wq, w0, aq0); aq1 = fmaf(wq, w1, aq1); aq2 = fmaf(wq, w2, aq2);
    }
    int base = a * (IDM_ * RR_) + d * RR_;
    g_M[0][base + 0] = ak0; g_M[0][base + 1] = ak1; g_M[0][base + 2] = ak2;
    g_M[1][base + 0] = aq0; g_M[1][base + 1] = aq1; g_M[1][base + 2] = aq2;

    if (d < RR_) {   // folded bias: c[r] = sum_e b[e] * W[a,e,r]
        float sk = 0.f, sq = 0.f;
        for (int e = 0; e < IDM_; e++) {
            sk = fmaf(bk[e], Wsh[e * 3 + d], sk);
            sq = fmaf(bq[e], Wsh[e * 3 + d], sq);
        }
        g_c[0][a * RR_ + d] = sk;
        g_c[1][a * RR_ + d] = sq;
    }
}

// ---------------------------------------------------------------------------
// Kernel 2: compute hash codes.  One warp per sequence row (K and Q).
// Kc pre-scaled by 1/R so the main kernel's dot needs no extra multiply.
// ---------------------------------------------------------------------------
__global__ void code_kernel(const float* __restrict__ K, const float* __restrict__ Q) {
    int warp = (blockIdx.x * blockDim.x + threadIdx.x) >> 5;
    int lane = threadIdx.x & 31;
    int which = (warp >= A_ * SK_) ? 1 : 0;
    int row   = which ? (warp - A_ * SK_) : warp;     // a*2048 + s
    int a     = row >> 11;

    const float* X = which ? Q : K;
    const float4 x = reinterpret_cast<const float4*>(X)[row * (D_ / 4) + lane];

    const float* M = &g_M[which][a * (IDM_ * RR_) + lane * 12];   // 48B aligned
    float4 m0 = *reinterpret_cast<const float4*>(M);
    float4 m1 = *reinterpret_cast<const float4*>(M + 4);
    float4 m2 = *reinterpret_cast<const float4*>(M + 8);

    // partial dots for r = 0,1,2  (M layout d-major: [d0r0 d0r1 d0r2 d1r0 ...])
    float p0 = x.x * m0.x + x.y * m0.w + x.z * m1.z + x.w * m2.y;
    float p1 = x.x * m0.y + x.y * m1.x + x.z * m1.w + x.w * m2.z;
    float p2 = x.x * m0.z + x.y * m1.y + x.z * m2.x + x.w * m2.w;

#pragma unroll
    for (int o = 16; o > 0; o >>= 1) {
        p0 += __shfl_xor_sync(0xffffffffu, p0, o);
        p1 += __shfl_xor_sync(0xffffffffu, p1, o);
        p2 += __shfl_xor_sync(0xffffffffu, p2, o);
    }
    if (lane == 0) {
        const float* c = &g_c[which][a * RR_];
        float scale = which ? 1.0f : (1.0f / 3.0f);   // fold /R into Kc
        float v0 = tanhf((p0 + c[0]) * 0.1f) * scale;
        float v1 = tanhf((p1 + c[1]) * 0.1f) * scale;
        float v2 = tanhf((p2 + c[2]) * 0.1f) * scale;
        g_code[which][row] = make_float4(v0, v1, v2, 0.f);
    }
}

// ---------------------------------------------------------------------------
// Kernel 3: main pass.  out[a,t,s] = x * sigmoid(x/10),  x = Qc(t)·Kc(s)/R.
// |x| < 1  =>  sigmoid(x/10) ~= 0.5 + (x/10)/4 - (x/10)^3/48   (abs err ~2e-8)
// Tile: 8 t-rows x 1024 s-cols per 256-thread block; float4 coalesced stores.
// ---------------------------------------------------------------------------
__device__ __forceinline__ float pc_fn(const float4 q, const float4 k) {
    float x  = fmaf(q.x, k.x, fmaf(q.y, k.y, q.z * k.z));     // Kc already /3
    float t  = x * x;
    float sg = fmaf(x, fmaf(t, -2.0833333e-5f, 0.025f), 0.5f); // sigmoid(x/10)
    return x * sg;
}

__global__ void __launch_bounds__(256) pc_kernel(float* __restrict__ out) {
    const int a     = blockIdx.z;
    const int tbase = blockIdx.y * 8;
    const int sbase = blockIdx.x * 1024;
    const int tid   = threadIdx.x;

    __shared__ float4 kc_sh[1024];
    __shared__ float4 qc_sh[8];

#pragma unroll
    for (int i = 0; i < 4; i++)
        kc_sh[tid + 256 * i] = g_code[0][a * SK_ + sbase + tid + 256 * i];
    if (tid < 8)
        qc_sh[tid] = g_code[1][a * SQ_ + tbase + tid];
    __syncthreads();

    const float4 k0 = kc_sh[tid * 4 + 0];
    const float4 k1 = kc_sh[tid * 4 + 1];
    const float4 k2 = kc_sh[tid * 4 + 2];
    const float4 k3 = kc_sh[tid * 4 + 3];

    size_t obase = ((size_t)(a * SQ_ + tbase)) * SK_ + (size_t)(sbase + tid * 4);
#pragma unroll
    for (int j = 0; j < 8; j++) {
        const float4 q = qc_sh[j];        // broadcast LDS
        float4 o;
        o.x = pc_fn(q, k0);
        o.y = pc_fn(q, k1);
        o.z = pc_fn(q, k2);
        o.w = pc_fn(q, k3);
        *reinterpret_cast<float4*>(out + obase + (size_t)j * SK_) = o;
    }
}

// ---------------------------------------------------------------------------
// Launch
// ---------------------------------------------------------------------------
extern "C" void kernel_launch(void* const* d_in, const int* in_sizes, int n_in,
                              void* d_out, int out_size) {
    const float* K  = (const float*)d_in[0];
    const float* Q  = (const float*)d_in[1];
    const float* Wk = (const float*)d_in[2];
    const float* bk = (const float*)d_in[3];
    const float* Wq = (const float*)d_in[4];
    const float* bq = (const float*)d_in[5];
    const float* W  = (const float*)d_in[6];
    float* out = (float*)d_out;

    prep_kernel<<<A_, IDM_>>>(Wk, bk, Wq, bq, W);
    // 2 * 16 * 2048 rows, 1 warp per row, 8 warps per block
    code_kernel<<<(2 * A_ * SK_) / 8, 256>>>(K, Q);
    pc_kernel<<<dim3(SK_ / 1024, SQ_ / 8, A_), 256>>>(out);
}

// round 2
// speedup vs baseline: 1.2057x; 1.2057x over previous
#include <cuda_runtime.h>
#include <math.h>

// Problem constants (fixed by the dataset)
#define A_   16
#define SK_  2048
#define SQ_  2048
#define D_   128
#define IDM_ 128
#define RR_  3
// T_ANNEAL = 10, t_ANNEAL = 0

// ---------------------------------------------------------------------------
// Scratch (device globals — no allocation allowed)
// ---------------------------------------------------------------------------
// Folded projection matrices: M[side][a][d][r] = sum_e Wx[e,d] * W[a,e,r]
// layout: a*384 + d*3 + r
__device__ float  g_M[2][A_ * IDM_ * RR_];   // [0] = K-side, [1] = Q-side
__device__ float  g_c[2][A_ * RR_];          // folded bias projections
// Hash codes, padded to float4 per row.  K-codes pre-scaled by 1/R.
__device__ float4 g_code[2][A_ * SK_];       // [0] = Kc/3, [1] = Qc

// ---------------------------------------------------------------------------
// Kernel 1: fold Wk/Wq + bias through W[a].
// Grid: 32 blocks = (side, a).  Block: 512 threads = (epart 0..3, d 0..127).
// Each thread reduces 32 e's; 4 partials combined through shared memory.
// ---------------------------------------------------------------------------
__global__ void __launch_bounds__(512) prep_kernel(
        const float* __restrict__ Wk, const float* __restrict__ bk,
        const float* __restrict__ Wq, const float* __restrict__ bq,
        const float* __restrict__ W) {
    const int side = blockIdx.x >> 4;        // 0 = K, 1 = Q
    const int a    = blockIdx.x & 15;
    const float* Wx = side ? Wq : Wk;
    const float* bx = side ? bq : bk;

    const int t  = threadIdx.x;
    const int d  = t & 127;
    const int ep = t >> 7;                   // e-partition 0..3

    __shared__ float Wsh[IDM_ * RR_];        // W[a] : [128,3]
    __shared__ float red[4][IDM_ * RR_];     // partial sums

    for (int i = t; i < IDM_ * RR_; i += 512) Wsh[i] = W[a * IDM_ * RR_ + i];
    __syncthreads();

    float a0 = 0.f, a1 = 0.f, a2 = 0.f;
#pragma unroll 8
    for (int i = 0; i < 32; i++) {
        int e = ep * 32 + i;
        float w = Wx[e * D_ + d];            // coalesced; same e per warp -> Wsh broadcast
        a0 = fmaf(w, Wsh[e * 3 + 0], a0);
        a1 = fmaf(w, Wsh[e * 3 + 1], a1);
        a2 = fmaf(w, Wsh[e * 3 + 2], a2);
    }
    red[ep][d * 3 + 0] = a0;
    red[ep][d * 3 + 1] = a1;
    red[ep][d * 3 + 2] = a2;
    __syncthreads();

    if (ep == 0) {
        int base = a * (IDM_ * RR_) + d * RR_;
#pragma unroll
        for (int r = 0; r < RR_; r++) {
            int i = d * 3 + r;
            g_M[side][base + r] = red[0][i] + red[1][i] + red[2][i] + red[3][i];
        }
    }

    // bias fold: warp 0 computes c[r] = sum_e b[e] * W[a,e,r]
    if (t < 32) {
        float c0 = 0.f, c1 = 0.f, c2 = 0.f;
#pragma unroll
        for (int e = t; e < IDM_; e += 32) {
            float b = bx[e];
            c0 = fmaf(b, Wsh[e * 3 + 0], c0);
            c1 = fmaf(b, Wsh[e * 3 + 1], c1);
            c2 = fmaf(b, Wsh[e * 3 + 2], c2);
        }
#pragma unroll
        for (int o = 16; o > 0; o >>= 1) {
            c0 += __shfl_xor_sync(0xffffffffu, c0, o);
            c1 += __shfl_xor_sync(0xffffffffu, c1, o);
            c2 += __shfl_xor_sync(0xffffffffu, c2, o);
        }
        if (t == 0) {
            g_c[side][a * RR_ + 0] = c0;
            g_c[side][a * RR_ + 1] = c1;
            g_c[side][a * RR_ + 2] = c2;
        }
    }
}

// ---------------------------------------------------------------------------
// Kernel 2: compute hash codes.  One warp per sequence row (K and Q).
// Kc pre-scaled by 1/R so the main kernel's dot needs no extra multiply.
// ---------------------------------------------------------------------------
__global__ void code_kernel(const float* __restrict__ K, const float* __restrict__ Q) {
    int warp = (blockIdx.x * blockDim.x + threadIdx.x) >> 5;
    int lane = threadIdx.x & 31;
    int which = (warp >= A_ * SK_) ? 1 : 0;
    int row   = which ? (warp - A_ * SK_) : warp;     // a*2048 + s
    int a     = row >> 11;

    const float* X = which ? Q : K;
    const float4 x = reinterpret_cast<const float4*>(X)[row * (D_ / 4) + lane];

    const float* M = &g_M[which][a * (IDM_ * RR_) + lane * 12];
    float4 m0 = *reinterpret_cast<const float4*>(M);
    float4 m1 = *reinterpret_cast<const float4*>(M + 4);
    float4 m2 = *reinterpret_cast<const float4*>(M + 8);

    // partial dots for r = 0,1,2  (M layout d-major: [d0r0 d0r1 d0r2 d1r0 ...])
    float p0 = x.x * m0.x + x.y * m0.w + x.z * m1.z + x.w * m2.y;
    float p1 = x.x * m0.y + x.y * m1.x + x.z * m1.w + x.w * m2.z;
    float p2 = x.x * m0.z + x.y * m1.y + x.z * m2.x + x.w * m2.w;

#pragma unroll
    for (int o = 16; o > 0; o >>= 1) {
        p0 += __shfl_xor_sync(0xffffffffu, p0, o);
        p1 += __shfl_xor_sync(0xffffffffu, p1, o);
        p2 += __shfl_xor_sync(0xffffffffu, p2, o);
    }
    if (lane == 0) {
        const float* c = &g_c[which][a * RR_];
        float scale = which ? 1.0f : (1.0f / 3.0f);   // fold /R into Kc
        float v0 = tanhf((p0 + c[0]) * 0.1f) * scale;
        float v1 = tanhf((p1 + c[1]) * 0.1f) * scale;
        float v2 = tanhf((p2 + c[2]) * 0.1f) * scale;
        g_code[which][row] = make_float4(v0, v1, v2, 0.f);
    }
}

// ---------------------------------------------------------------------------
// Kernel 3: main pass.  out[a,t,s] = x * sigmoid(x/10),  x = Qc(t)·Kc(s)/R.
// |x| < 1  =>  sigmoid(x/10) ~= 0.5 + (x/10)/4 - (x/10)^3/48   (abs err ~2e-8)
// Tile: 8 t-rows x 1024 s-cols per 256-thread block; float4 coalesced stores.
// ---------------------------------------------------------------------------
__device__ __forceinline__ float pc_fn(const float4 q, const float4 k) {
    float x  = fmaf(q.x, k.x, fmaf(q.y, k.y, q.z * k.z));      // Kc already /3
    float t  = x * x;
    float sg = fmaf(x, fmaf(t, -2.0833333e-5f, 0.025f), 0.5f); // sigmoid(x/10)
    return x * sg;
}

__global__ void __launch_bounds__(256) pc_kernel(float* __restrict__ out) {
    const int a     = blockIdx.z;
    const int tbase = blockIdx.y * 8;
    const int sbase = blockIdx.x * 1024;
    const int tid   = threadIdx.x;

    __shared__ float4 kc_sh[1024];
    __shared__ float4 qc_sh[8];

#pragma unroll
    for (int i = 0; i < 4; i++)
        kc_sh[tid + 256 * i] = g_code[0][a * SK_ + sbase + tid + 256 * i];
    if (tid < 8)
        qc_sh[tid] = g_code[1][a * SQ_ + tbase + tid];
    __syncthreads();

    const float4 k0 = kc_sh[tid * 4 + 0];
    const float4 k1 = kc_sh[tid * 4 + 1];
    const float4 k2 = kc_sh[tid * 4 + 2];
    const float4 k3 = kc_sh[tid * 4 + 3];

    size_t obase = ((size_t)(a * SQ_ + tbase)) * SK_ + (size_t)(sbase + tid * 4);
#pragma unroll
    for (int j = 0; j < 8; j++) {
        const float4 q = qc_sh[j];        // broadcast LDS
        float4 o;
        o.x = pc_fn(q, k0);
        o.y = pc_fn(q, k1);
        o.z = pc_fn(q, k2);
        o.w = pc_fn(q, k3);
        *reinterpret_cast<float4*>(out + obase + (size_t)j * SK_) = o;
    }
}

// ---------------------------------------------------------------------------
// Launch
// ---------------------------------------------------------------------------
extern "C" void kernel_launch(void* const* d_in, const int* in_sizes, int n_in,
                              void* d_out, int out_size) {
    const float* K  = (const float*)d_in[0];
    const float* Q  = (const float*)d_in[1];
    const float* Wk = (const float*)d_in[2];
    const float* bk = (const float*)d_in[3];
    const float* Wq = (const float*)d_in[4];
    const float* bq = (const float*)d_in[5];
    const float* W  = (const float*)d_in[6];
    float* out = (float*)d_out;

    prep_kernel<<<2 * A_, 512>>>(Wk, bk, Wq, bq, W);
    // 2 * 16 * 2048 rows, 1 warp per row, 8 warps per block
    code_kernel<<<(2 * A_ * SK_) / 8, 256>>>(K, Q);
    pc_kernel<<<dim3(SK_ / 1024, SQ_ / 8, A_), 256>>>(out);
}